// round 12
// baseline (speedup 1.0000x reference)
#include <cuda_runtime.h>
#include <cuda_fp16.h>
#include <math.h>
#include <float.h>

// Problem constants
#define B_   8
#define L_   2048
#define LOG2L 11
#define D_   512
#define DM_  512
#define KTOP 15

// ---------------- device scratch (static allocation only) ----------------
__device__ float g_qT[B_ * D_ * L_];   // (B, D, L)
__device__ float g_kT[B_ * D_ * L_];
__device__ float g_vT[B_ * D_ * L_];
__device__ float g_AT[B_ * D_ * L_];
__device__ float2 g_tw[L_ / 2];        // exp(-2*pi*i*j/L)

// ---------------- twiddle init ----------------
__global__ void twiddle_init_kernel() {
    int j = blockIdx.x * blockDim.x + threadIdx.x;
    if (j < L_ / 2) {
        float sn, cs;
        sincospif((float)j / 1024.0f, &sn, &cs);
        g_tw[j] = make_float2(cs, -sn);
    }
}

// ---------------- FP16 split helpers ----------------
__device__ __forceinline__ unsigned pack_hi(float a, float b) {
    __half2 h = __halves2half2(__float2half_rn(a), __float2half_rn(b));
    return *(unsigned*)&h;
}
__device__ __forceinline__ unsigned pack_lo(float a, float b) {
    float ra = a - __half2float(__float2half_rn(a));
    float rb = b - __half2float(__float2half_rn(b));
    __half2 h = __halves2half2(__float2half_rn(ra), __float2half_rn(rb));
    return *(unsigned*)&h;
}

__device__ __forceinline__ void mma_f16(float c[4], const unsigned a[4], const unsigned b[2]) {
    asm volatile(
        "mma.sync.aligned.m16n8k16.row.col.f32.f16.f16.f32 "
        "{%0,%1,%2,%3}, {%4,%5,%6,%7}, {%8,%9}, {%0,%1,%2,%3};\n"
        : "+f"(c[0]), "+f"(c[1]), "+f"(c[2]), "+f"(c[3])
        : "r"(a[0]), "r"(a[1]), "r"(a[2]), "r"(a[3]), "r"(b[0]), "r"(b[1]));
}

// ---------------- Fused 3-GEMM (fp16 split x3 products, fp32 accum) ----------------
// EXACT r5 champion version. out^T[b,d,t] = X @ W + bias. CTA tile 128(t) x 128(d),
// K-tile 16. 8 warps as 2(m) x 4(n); warp tile 64x32; mma m16n8k16.
__global__ __launch_bounds__(256, 2)
void gemm3_fp16_kernel(const float* __restrict__ Qi, const float* __restrict__ Ki,
                       const float* __restrict__ Vi,
                       const float* __restrict__ WQ, const float* __restrict__ WK,
                       const float* __restrict__ WV,
                       const float* __restrict__ bQ, const float* __restrict__ bK,
                       const float* __restrict__ bV) {
    const int z = blockIdx.z;
    const float* X    = (z == 0) ? Qi : ((z == 1) ? Ki : Vi);
    const float* W    = (z == 0) ? WQ : ((z == 1) ? WK : WV);
    const float* bias = (z == 0) ? bQ : ((z == 1) ? bK : bV);
    float* outT       = (z == 0) ? g_qT : ((z == 1) ? g_kT : g_vT);

    __shared__ unsigned As2h[128][9], As2l[128][9];
    __shared__ unsigned Bs2h[8][132], Bs2l[8][132];

    const int tid = threadIdx.x;
    const int lane = tid & 31;
    const int w = tid >> 5;
    const int wm0 = (w & 1) * 64;
    const int wn0 = (w >> 1) * 32;
    const int g = lane >> 2;    // 0..7
    const int c = lane & 3;     // 0..3
    const int m0 = blockIdx.x * 128;
    const int n0 = blockIdx.y * 128;

    const int rowA = tid >> 2;             // 0..63 (and +64)
    const int kqA  = (tid & 3) << 2;       // 0,4,8,12
    const int pB   = tid >> 5;             // 0..7 (kpair)
    const int nqB  = (lane) << 2;          // 0..124
    const float* pA0 = &X[(size_t)(m0 + rowA) * DM_ + kqA];
    const float* pA1 = pA0 + (size_t)64 * DM_;
    const float* pB0 = &W[(size_t)(2 * pB) * D_ + n0 + nqB];
    const float* pB1 = pB0 + D_;

    float cacc[4][4][4];
#pragma unroll
    for (int mt = 0; mt < 4; mt++)
#pragma unroll
        for (int nt = 0; nt < 4; nt++)
#pragma unroll
            for (int i = 0; i < 4; i++) cacc[mt][nt][i] = 0.0f;

    float4 av0 = *(const float4*)pA0;
    float4 av1 = *(const float4*)pA1;
    float4 bv0 = *(const float4*)pB0;
    float4 bv1 = *(const float4*)pB1;

#pragma unroll 1
    for (int k0 = 0; k0 < DM_; k0 += 16) {
        const int kp = kqA >> 1;
        As2h[rowA][kp]          = pack_hi(av0.x, av0.y);
        As2h[rowA][kp + 1]      = pack_hi(av0.z, av0.w);
        As2l[rowA][kp]          = pack_lo(av0.x, av0.y);
        As2l[rowA][kp + 1]      = pack_lo(av0.z, av0.w);
        As2h[rowA + 64][kp]     = pack_hi(av1.x, av1.y);
        As2h[rowA + 64][kp + 1] = pack_hi(av1.z, av1.w);
        As2l[rowA + 64][kp]     = pack_lo(av1.x, av1.y);
        As2l[rowA + 64][kp + 1] = pack_lo(av1.z, av1.w);
        {
            uint4 uh = make_uint4(pack_hi(bv0.x, bv1.x), pack_hi(bv0.y, bv1.y),
                                  pack_hi(bv0.z, bv1.z), pack_hi(bv0.w, bv1.w));
            uint4 ul = make_uint4(pack_lo(bv0.x, bv1.x), pack_lo(bv0.y, bv1.y),
                                  pack_lo(bv0.z, bv1.z), pack_lo(bv0.w, bv1.w));
            *(uint4*)&Bs2h[pB][nqB] = uh;
            *(uint4*)&Bs2l[pB][nqB] = ul;
        }
        __syncthreads();

        if (k0 + 16 < DM_) {
            av0 = *(const float4*)(pA0 + k0 + 16);
            av1 = *(const float4*)(pA1 + k0 + 16);
            bv0 = *(const float4*)(pB0 + (size_t)(k0 + 16) * D_);
            bv1 = *(const float4*)(pB1 + (size_t)(k0 + 16) * D_);
        }

        unsigned bh[4][2], bl[4][2];
#pragma unroll
        for (int nt = 0; nt < 4; nt++) {
            int cn = wn0 + nt * 8 + g;
            bh[nt][0] = Bs2h[c][cn];
            bh[nt][1] = Bs2h[c + 4][cn];
            bl[nt][0] = Bs2l[c][cn];
            bl[nt][1] = Bs2l[c + 4][cn];
        }
#pragma unroll
        for (int mt = 0; mt < 4; mt++) {
            int row = wm0 + mt * 16 + g;
            unsigned ah[4], al[4];
            ah[0] = As2h[row][c];
            ah[1] = As2h[row + 8][c];
            ah[2] = As2h[row][c + 4];
            ah[3] = As2h[row + 8][c + 4];
            al[0] = As2l[row][c];
            al[1] = As2l[row + 8][c];
            al[2] = As2l[row][c + 4];
            al[3] = As2l[row + 8][c + 4];
#pragma unroll
            for (int nt = 0; nt < 4; nt++) {
                mma_f16(cacc[mt][nt], ah, bl[nt]);
                mma_f16(cacc[mt][nt], al, bh[nt]);
                mma_f16(cacc[mt][nt], ah, bh[nt]);
            }
        }
        __syncthreads();
    }

    const int b = m0 >> LOG2L;
    const int tbase = (m0 & (L_ - 1)) + wm0 + g;
#pragma unroll
    for (int nt = 0; nt < 4; nt++) {
        const int d0 = n0 + wn0 + nt * 8 + 2 * c;
        const float bi0 = bias[d0];
        const float bi1 = bias[d0 + 1];
        const size_t row0 = ((size_t)(b * D_ + d0) << LOG2L);
        const size_t row1 = row0 + L_;
#pragma unroll
        for (int mt = 0; mt < 4; mt++) {
            const int t = tbase + mt * 16;
            outT[row0 + t]     = cacc[mt][nt][0] + bi0;
            outT[row1 + t]     = cacc[mt][nt][1] + bi1;
            outT[row0 + t + 8] = cacc[mt][nt][2] + bi0;
            outT[row1 + t + 8] = cacc[mt][nt][3] + bi1;
        }
    }
}

// ---------------- complex helpers ----------------
__device__ __forceinline__ float2 cmul(float2 a, float2 b) {
    return make_float2(a.x * b.x - a.y * b.y, a.x * b.y + a.y * b.x);
}
__device__ __forceinline__ float2 cmulc(float2 a, float2 b) {   // a * conj(b)
    return make_float2(a.x * b.x + a.y * b.y, a.y * b.x - a.x * b.y);
}
__device__ __forceinline__ float2 cadd(float2 a, float2 b) { return make_float2(a.x + b.x, a.y + b.y); }
__device__ __forceinline__ float2 csub(float2 a, float2 b) { return make_float2(a.x - b.x, a.y - b.y); }

#define ZI(i) ((i) + ((i) >> 5))

// ---------------- fused FFT-correlation + top-k + softmax + gather ----------------
// r11 champion corr kernel; occupancy experiment: launch_bounds(256,4) + host-side
// carveout=100% so 4 CTAs/SM (164KB smem) become resident.
__global__ __launch_bounds__(256, 4)
void corr_attn_kernel() {
    __shared__ float2 tw[L_ / 2];          // 8 KB
    __shared__ float2 z[L_ + L_ / 32];     // 16.5 KB (fwd FFT; reused as v column)
    __shared__ float2 s[L_ + L_ / 32];     // 16.5 KB (spectrum + inverse FFT)
    __shared__ float  red_v[16];
    __shared__ int    red_i[16];

    const int tid = threadIdx.x;
    const int lane = tid & 31;
    const int warp = tid >> 5;
    const int bd = blockIdx.x;
    const size_t col = (size_t)bd << LOG2L;

    const int l32 = lane;
    const int c32 = l32 + (tid >> 5) * 256;
    const int t1 = tid & 3;
    const int c4 = t1 + (tid >> 2) * 32;
    const int base8 = tid * 8;

    for (int i = tid; i < L_ / 2; i += 256) tw[i] = g_tw[i];

    float2 zr[8];
#pragma unroll
    for (int q = 0; q < 8; q++)
        zr[q] = make_float2(g_qT[col + tid + 256 * q], g_kT[col + tid + 256 * q]);
    __syncthreads();

    // ======== forward DIF ========
    // group 1: stride-256, spans 1024/512/256
#pragma unroll
    for (int q = 0; q < 4; q++) {
        float2 a = zr[q], b = zr[q + 4];
        float2 wv = tw[tid + 256 * q];
        zr[q] = cadd(a, b);
        zr[q + 4] = cmul(csub(a, b), wv);
    }
#pragma unroll
    for (int gg = 0; gg < 8; gg += 4)
#pragma unroll
        for (int q = 0; q < 2; q++) {
            float2 a = zr[gg + q], b = zr[gg + q + 2];
            float2 wv = tw[(tid + 256 * q) << 1];
            zr[gg + q] = cadd(a, b);
            zr[gg + q + 2] = cmul(csub(a, b), wv);
        }
    {
        float2 wv = tw[tid << 2];
#pragma unroll
        for (int p = 0; p < 8; p += 2) {
            float2 a = zr[p], b = zr[p + 1];
            zr[p] = cadd(a, b);
            zr[p + 1] = cmul(csub(a, b), wv);
        }
    }
#pragma unroll
    for (int q = 0; q < 8; q++) z[ZI(tid + 256 * q)] = zr[q];
    __syncthreads();

    // group 2: stride-32, spans 128/64/32
#pragma unroll
    for (int q = 0; q < 8; q++) zr[q] = z[ZI(c32 + 32 * q)];
#pragma unroll
    for (int q = 0; q < 4; q++) {
        float2 a = zr[q], b = zr[q + 4];
        float2 wv = tw[(l32 + 32 * q) << 3];
        zr[q] = cadd(a, b);
        zr[q + 4] = cmul(csub(a, b), wv);
    }
#pragma unroll
    for (int gg = 0; gg < 8; gg += 4)
#pragma unroll
        for (int q = 0; q < 2; q++) {
            float2 a = zr[gg + q], b = zr[gg + q + 2];
            float2 wv = tw[(l32 + 32 * q) << 4];
            zr[gg + q] = cadd(a, b);
            zr[gg + q + 2] = cmul(csub(a, b), wv);
        }
    {
        float2 wv = tw[l32 << 5];
#pragma unroll
        for (int p = 0; p < 8; p += 2) {
            float2 a = zr[p], b = zr[p + 1];
            zr[p] = cadd(a, b);
            zr[p + 1] = cmul(csub(a, b), wv);
        }
    }
#pragma unroll
    for (int q = 0; q < 8; q++) z[ZI(c32 + 32 * q)] = zr[q];
    __syncthreads();

    // group 3: stride-4, spans 16/8/4
#pragma unroll
    for (int q = 0; q < 8; q++) zr[q] = z[ZI(c4 + 4 * q)];
#pragma unroll
    for (int q = 0; q < 4; q++) {
        float2 a = zr[q], b = zr[q + 4];
        float2 wv = tw[(t1 + 4 * q) << 6];
        zr[q] = cadd(a, b);
        zr[q + 4] = cmul(csub(a, b), wv);
    }
#pragma unroll
    for (int gg = 0; gg < 8; gg += 4)
#pragma unroll
        for (int q = 0; q < 2; q++) {
            float2 a = zr[gg + q], b = zr[gg + q + 2];
            float2 wv = tw[(t1 + 4 * q) << 7];
            zr[gg + q] = cadd(a, b);
            zr[gg + q + 2] = cmul(csub(a, b), wv);
        }
    {
        float2 wv = tw[t1 << 8];
#pragma unroll
        for (int p = 0; p < 8; p += 2) {
            float2 a = zr[p], b = zr[p + 1];
            zr[p] = cadd(a, b);
            zr[p + 1] = cmul(csub(a, b), wv);
        }
    }
#pragma unroll
    for (int q = 0; q < 8; q++) z[ZI(c4 + 4 * q)] = zr[q];
    __syncthreads();

    // group 4: contiguous, spans 2/1
#pragma unroll
    for (int q = 0; q < 8; q++) zr[q] = z[ZI(base8 + q)];
#pragma unroll
    for (int gg = 0; gg < 8; gg += 4)
#pragma unroll
        for (int q = 0; q < 2; q++) {
            float2 a = zr[gg + q], b = zr[gg + q + 2];
            float2 wv = tw[(q & 1) << 9];
            zr[gg + q] = cadd(a, b);
            zr[gg + q + 2] = cmul(csub(a, b), wv);
        }
#pragma unroll
    for (int p = 0; p < 8; p += 2) {
        float2 a = zr[p], b = zr[p + 1];
        zr[p] = cadd(a, b);
        zr[p + 1] = csub(a, b);
    }
#pragma unroll
    for (int q = 0; q < 8; q++) z[ZI(base8 + q)] = zr[q];
    __syncthreads();

    // ======== cross-spectrum (bit-reversed domain; z -> s) ========
    const float scl = 0.25f / (float)L_;
    for (int p = tid; p < L_; p += 256) {
        int f = __brev((unsigned)p) >> 21;
        int fm = (L_ - f) & (L_ - 1);
        int pm = __brev((unsigned)fm) >> 21;
        float2 Zf = z[ZI(p)], Zm = z[ZI(pm)];
        float2 u = make_float2(Zf.x + Zm.x, Zf.y - Zm.y);
        float2 v = make_float2(Zf.x - Zm.x, -Zf.y - Zm.y);
        float2 pr = cmul(u, v);
        s[ZI(p)] = make_float2(-pr.y * scl, pr.x * scl);
    }
    __syncthreads();   // all xspec reads of z done -> z reusable

    // hoisted v-column load (reuses z; overlaps the inverse FFT)
    float* vcol = (float*)z;
    for (int i = tid; i < L_; i += 256) vcol[i] = g_vT[col + i];

    // ======== inverse DIT (in s) ========
    float2 sr[8];
    // group 4': contiguous, spans 1/2
#pragma unroll
    for (int q = 0; q < 8; q++) sr[q] = s[ZI(base8 + q)];
#pragma unroll
    for (int p = 0; p < 8; p += 2) {
        float2 a = sr[p], b = sr[p + 1];
        sr[p] = cadd(a, b);
        sr[p + 1] = csub(a, b);
    }
#pragma unroll
    for (int gg = 0; gg < 8; gg += 4)
#pragma unroll
        for (int q = 0; q < 2; q++) {
            float2 wv = tw[(q & 1) << 9];
            float2 bw = cmulc(sr[gg + q + 2], wv);
            float2 a = sr[gg + q];
            sr[gg + q] = cadd(a, bw);
            sr[gg + q + 2] = csub(a, bw);
        }
#pragma unroll
    for (int q = 0; q < 8; q++) s[ZI(base8 + q)] = sr[q];
    __syncthreads();

    // group 3': stride-4, spans 4/8/16
#pragma unroll
    for (int q = 0; q < 8; q++) sr[q] = s[ZI(c4 + 4 * q)];
    {
        float2 wv = tw[t1 << 8];
#pragma unroll
        for (int p = 0; p < 8; p += 2) {
            float2 bw = cmulc(sr[p + 1], wv);
            float2 a = sr[p];
            sr[p] = cadd(a, bw);
            sr[p + 1] = csub(a, bw);
        }
    }
#pragma unroll
    for (int gg = 0; gg < 8; gg += 4)
#pragma unroll
        for (int q = 0; q < 2; q++) {
            float2 wv = tw[(t1 + 4 * q) << 7];
            float2 bw = cmulc(sr[gg + q + 2], wv);
            float2 a = sr[gg + q];
            sr[gg + q] = cadd(a, bw);
            sr[gg + q + 2] = csub(a, bw);
        }
#pragma unroll
    for (int q = 0; q < 4; q++) {
        float2 wv = tw[(t1 + 4 * q) << 6];
        float2 bw = cmulc(sr[q + 4], wv);
        float2 a = sr[q];
        sr[q] = cadd(a, bw);
        sr[q + 4] = csub(a, bw);
    }
#pragma unroll
    for (int q = 0; q < 8; q++) s[ZI(c4 + 4 * q)] = sr[q];
    __syncthreads();

    // group 2': stride-32, spans 32/64/128
#pragma unroll
    for (int q = 0; q < 8; q++) sr[q] = s[ZI(c32 + 32 * q)];
    {
        float2 wv = tw[l32 << 5];
#pragma unroll
        for (int p = 0; p < 8; p += 2) {
            float2 bw = cmulc(sr[p + 1], wv);
            float2 a = sr[p];
            sr[p] = cadd(a, bw);
            sr[p + 1] = csub(a, bw);
        }
    }
#pragma unroll
    for (int gg = 0; gg < 8; gg += 4)
#pragma unroll
        for (int q = 0; q < 2; q++) {
            float2 wv = tw[(l32 + 32 * q) << 4];
            float2 bw = cmulc(sr[gg + q + 2], wv);
            float2 a = sr[gg + q];
            sr[gg + q] = cadd(a, bw);
            sr[gg + q + 2] = csub(a, bw);
        }
#pragma unroll
    for (int q = 0; q < 4; q++) {
        float2 wv = tw[(l32 + 32 * q) << 3];
        float2 bw = cmulc(sr[q + 4], wv);
        float2 a = sr[q];
        sr[q] = cadd(a, bw);
        sr[q + 4] = csub(a, bw);
    }
#pragma unroll
    for (int q = 0; q < 8; q++) s[ZI(c32 + 32 * q)] = sr[q];
    __syncthreads();

    // group 1': stride-256, spans 256/512/1024 (feeds top-k in registers)
#pragma unroll
    for (int q = 0; q < 8; q++) sr[q] = s[ZI(tid + 256 * q)];
    {
        float2 wv = tw[tid << 2];
#pragma unroll
        for (int p = 0; p < 8; p += 2) {
            float2 bw = cmulc(sr[p + 1], wv);
            float2 a = sr[p];
            sr[p] = cadd(a, bw);
            sr[p + 1] = csub(a, bw);
        }
    }
#pragma unroll
    for (int gg = 0; gg < 8; gg += 4)
#pragma unroll
        for (int q = 0; q < 2; q++) {
            float2 wv = tw[(tid + 256 * q) << 1];
            float2 bw = cmulc(sr[gg + q + 2], wv);
            float2 a = sr[gg + q];
            sr[gg + q] = cadd(a, bw);
            sr[gg + q + 2] = csub(a, bw);
        }
#pragma unroll
    for (int q = 0; q < 4; q++) {
        float2 wv = tw[tid + 256 * q];
        float2 bw = cmulc(sr[q + 4], wv);
        float2 a = sr[q];
        sr[q] = cadd(a, bw);
        sr[q + 4] = csub(a, bw);
    }
    // sr[q].x = R[tid + 256q]

    // ---- top-15: r5 scheme (warp shuffle + slot-double-buffered cross-warp) ----
    float rv[8];
#pragma unroll
    for (int q = 0; q < 8; q++) rv[q] = sr[q].x;

    float wsel[KTOP];
    int isel[KTOP];
#pragma unroll 1
    for (int rnd = 0; rnd < KTOP; rnd++) {
        float best = rv[0];
        int bq = 0;
#pragma unroll
        for (int q = 1; q < 8; q++)
            if (rv[q] > best) { best = rv[q]; bq = q; }
        int bi = tid + bq * 256;
#pragma unroll
        for (int off = 16; off > 0; off >>= 1) {
            float ov = __shfl_xor_sync(0xffffffffu, best, off);
            int oi = __shfl_xor_sync(0xffffffffu, bi, off);
            if (ov > best || (ov == best && oi < bi)) { best = ov; bi = oi; }
        }
        const int slot = (rnd & 1) * 8;
        if (lane == 0) { red_v[slot + warp] = best; red_i[slot + warp] = bi; }
        __syncthreads();
        float gb = red_v[slot];
        int gi = red_i[slot];
#pragma unroll
        for (int ww = 1; ww < 8; ww++) {
            float ov = red_v[slot + ww];
            int oi = red_i[slot + ww];
            if (ov > gb || (ov == gb && oi < gi)) { gb = ov; gi = oi; }
        }
        wsel[rnd] = gb;
        isel[rnd] = gi;
        if ((gi & 255) == tid) rv[gi >> 8] = -FLT_MAX;   // exclude (register-local)
    }

    // ---- softmax over the 15 selected (redundant per thread) ----
    float m = wsel[0];
#pragma unroll
    for (int k = 1; k < KTOP; k++) m = fmaxf(m, wsel[k]);
    float sum = 0.0f;
    float wnorm[KTOP];
#pragma unroll
    for (int k = 0; k < KTOP; k++) { float e = __expf(wsel[k] - m); wnorm[k] = e; sum += e; }
    const float inv = 1.0f / sum;
#pragma unroll
    for (int k = 0; k < KTOP; k++) wnorm[k] *= inv;

    // ---- gather: A^T[b,d,l] = sum_k w[k] * v[(l + lag_k) mod L] ----
    for (int l = tid; l < L_; l += 256) {
        float acc = 0.0f;
#pragma unroll
        for (int k = 0; k < KTOP; k++)
            acc = fmaf(wnorm[k], vcol[(l + isel[k]) & (L_ - 1)], acc);
        g_AT[col + l] = acc;
    }
}

// ---------------- transpose (B, D, L) -> (B, L, D) ----------------
__global__ void transpose_kernel(float* __restrict__ A) {
    __shared__ float tile[32][33];
    const int b = blockIdx.z;
    const int l0 = blockIdx.x * 32;
    const int d0 = blockIdx.y * 32;
    const int tx = threadIdx.x, ty = threadIdx.y;
#pragma unroll
    for (int r = 0; r < 32; r += 8)
        tile[ty + r][tx] = g_AT[((size_t)(b * D_ + d0 + ty + r) << LOG2L) + l0 + tx];
    __syncthreads();
#pragma unroll
    for (int r = 0; r < 32; r += 8)
        A[((size_t)(b * L_ + l0 + ty + r)) * D_ + d0 + tx] = tile[tx][ty + r];
}

// ---------------- launch ----------------
extern "C" void kernel_launch(void* const* d_in, const int* in_sizes, int n_in,
                              void* d_out, int out_size) {
    const float* Q   = (const float*)d_in[0];
    const float* K   = (const float*)d_in[1];
    const float* V   = (const float*)d_in[2];
    const float* WQw = (const float*)d_in[3];
    const float* WQb = (const float*)d_in[4];
    const float* WKw = (const float*)d_in[5];
    const float* WKb = (const float*)d_in[6];
    const float* WVw = (const float*)d_in[7];
    const float* WVb = (const float*)d_in[8];
    float* out = (float*)d_out;

    // opt into maximum smem carveout so 4 corr CTAs (164KB) fit per SM
    cudaFuncSetAttribute(corr_attn_kernel,
                         cudaFuncAttributePreferredSharedMemoryCarveout, 100);
    cudaFuncSetAttribute(gemm3_fp16_kernel,
                         cudaFuncAttributePreferredSharedMemoryCarveout, 100);

    twiddle_init_kernel<<<4, 256>>>();

    dim3 ggrid(B_ * L_ / 128, D_ / 128, 3);   // (128, 4, 3)
    gemm3_fp16_kernel<<<ggrid, 256>>>(Q, K, V, WQw, WKw, WVw, WQb, WKb, WVb);

    corr_attn_kernel<<<B_ * D_, 256>>>();

    dim3 tgrid(L_ / 32, D_ / 32, B_);         // (64, 16, 8)
    transpose_kernel<<<tgrid, dim3(32, 8)>>>(out);
}

// round 13
// speedup vs baseline: 1.0518x; 1.0518x over previous
#include <cuda_runtime.h>
#include <cuda_fp16.h>
#include <math.h>
#include <float.h>

// Problem constants
#define B_   8
#define L_   2048
#define LOG2L 11
#define D_   512
#define DM_  512
#define KTOP 15

// ---------------- device scratch (static allocation only) ----------------
__device__ float g_qT[B_ * D_ * L_];   // (B, D, L)
__device__ float g_kT[B_ * D_ * L_];
__device__ float g_vT[B_ * D_ * L_];
__device__ float g_AT[B_ * D_ * L_];
__device__ float2 g_tw[L_ / 2];        // exp(-2*pi*i*j/L)

// ---------------- twiddle init ----------------
__global__ void twiddle_init_kernel() {
    int j = blockIdx.x * blockDim.x + threadIdx.x;
    if (j < L_ / 2) {
        float sn, cs;
        sincospif((float)j / 1024.0f, &sn, &cs);
        g_tw[j] = make_float2(cs, -sn);
    }
}

// ---------------- FP16 split helpers ----------------
__device__ __forceinline__ unsigned pack_hi(float a, float b) {
    __half2 h = __halves2half2(__float2half_rn(a), __float2half_rn(b));
    return *(unsigned*)&h;
}
__device__ __forceinline__ unsigned pack_lo(float a, float b) {
    float ra = a - __half2float(__float2half_rn(a));
    float rb = b - __half2float(__float2half_rn(b));
    __half2 h = __halves2half2(__float2half_rn(ra), __float2half_rn(rb));
    return *(unsigned*)&h;
}

__device__ __forceinline__ void mma_f16(float c[4], const unsigned a[4], const unsigned b[2]) {
    asm volatile(
        "mma.sync.aligned.m16n8k16.row.col.f32.f16.f16.f32 "
        "{%0,%1,%2,%3}, {%4,%5,%6,%7}, {%8,%9}, {%0,%1,%2,%3};\n"
        : "+f"(c[0]), "+f"(c[1]), "+f"(c[2]), "+f"(c[3])
        : "r"(a[0]), "r"(a[1]), "r"(a[2]), "r"(a[3]), "r"(b[0]), "r"(b[1]));
}

// ---------------- Fused 3-GEMM (fp16 split x3 products, fp32 accum) ----------------
// EXACT r5 champion version.
__global__ __launch_bounds__(256, 2)
void gemm3_fp16_kernel(const float* __restrict__ Qi, const float* __restrict__ Ki,
                       const float* __restrict__ Vi,
                       const float* __restrict__ WQ, const float* __restrict__ WK,
                       const float* __restrict__ WV,
                       const float* __restrict__ bQ, const float* __restrict__ bK,
                       const float* __restrict__ bV) {
    const int z = blockIdx.z;
    const float* X    = (z == 0) ? Qi : ((z == 1) ? Ki : Vi);
    const float* W    = (z == 0) ? WQ : ((z == 1) ? WK : WV);
    const float* bias = (z == 0) ? bQ : ((z == 1) ? bK : bV);
    float* outT       = (z == 0) ? g_qT : ((z == 1) ? g_kT : g_vT);

    __shared__ unsigned As2h[128][9], As2l[128][9];
    __shared__ unsigned Bs2h[8][132], Bs2l[8][132];

    const int tid = threadIdx.x;
    const int lane = tid & 31;
    const int w = tid >> 5;
    const int wm0 = (w & 1) * 64;
    const int wn0 = (w >> 1) * 32;
    const int g = lane >> 2;    // 0..7
    const int c = lane & 3;     // 0..3
    const int m0 = blockIdx.x * 128;
    const int n0 = blockIdx.y * 128;

    const int rowA = tid >> 2;
    const int kqA  = (tid & 3) << 2;
    const int pB   = tid >> 5;
    const int nqB  = (lane) << 2;
    const float* pA0 = &X[(size_t)(m0 + rowA) * DM_ + kqA];
    const float* pA1 = pA0 + (size_t)64 * DM_;
    const float* pB0 = &W[(size_t)(2 * pB) * D_ + n0 + nqB];
    const float* pB1 = pB0 + D_;

    float cacc[4][4][4];
#pragma unroll
    for (int mt = 0; mt < 4; mt++)
#pragma unroll
        for (int nt = 0; nt < 4; nt++)
#pragma unroll
            for (int i = 0; i < 4; i++) cacc[mt][nt][i] = 0.0f;

    float4 av0 = *(const float4*)pA0;
    float4 av1 = *(const float4*)pA1;
    float4 bv0 = *(const float4*)pB0;
    float4 bv1 = *(const float4*)pB1;

#pragma unroll 1
    for (int k0 = 0; k0 < DM_; k0 += 16) {
        const int kp = kqA >> 1;
        As2h[rowA][kp]          = pack_hi(av0.x, av0.y);
        As2h[rowA][kp + 1]      = pack_hi(av0.z, av0.w);
        As2l[rowA][kp]          = pack_lo(av0.x, av0.y);
        As2l[rowA][kp + 1]      = pack_lo(av0.z, av0.w);
        As2h[rowA + 64][kp]     = pack_hi(av1.x, av1.y);
        As2h[rowA + 64][kp + 1] = pack_hi(av1.z, av1.w);
        As2l[rowA + 64][kp]     = pack_lo(av1.x, av1.y);
        As2l[rowA + 64][kp + 1] = pack_lo(av1.z, av1.w);
        {
            uint4 uh = make_uint4(pack_hi(bv0.x, bv1.x), pack_hi(bv0.y, bv1.y),
                                  pack_hi(bv0.z, bv1.z), pack_hi(bv0.w, bv1.w));
            uint4 ul = make_uint4(pack_lo(bv0.x, bv1.x), pack_lo(bv0.y, bv1.y),
                                  pack_lo(bv0.z, bv1.z), pack_lo(bv0.w, bv1.w));
            *(uint4*)&Bs2h[pB][nqB] = uh;
            *(uint4*)&Bs2l[pB][nqB] = ul;
        }
        __syncthreads();

        if (k0 + 16 < DM_) {
            av0 = *(const float4*)(pA0 + k0 + 16);
            av1 = *(const float4*)(pA1 + k0 + 16);
            bv0 = *(const float4*)(pB0 + (size_t)(k0 + 16) * D_);
            bv1 = *(const float4*)(pB1 + (size_t)(k0 + 16) * D_);
        }

        unsigned bh[4][2], bl[4][2];
#pragma unroll
        for (int nt = 0; nt < 4; nt++) {
            int cn = wn0 + nt * 8 + g;
            bh[nt][0] = Bs2h[c][cn];
            bh[nt][1] = Bs2h[c + 4][cn];
            bl[nt][0] = Bs2l[c][cn];
            bl[nt][1] = Bs2l[c + 4][cn];
        }
#pragma unroll
        for (int mt = 0; mt < 4; mt++) {
            int row = wm0 + mt * 16 + g;
            unsigned ah[4], al[4];
            ah[0] = As2h[row][c];
            ah[1] = As2h[row + 8][c];
            ah[2] = As2h[row][c + 4];
            ah[3] = As2h[row + 8][c + 4];
            al[0] = As2l[row][c];
            al[1] = As2l[row + 8][c];
            al[2] = As2l[row][c + 4];
            al[3] = As2l[row + 8][c + 4];
#pragma unroll
            for (int nt = 0; nt < 4; nt++) {
                mma_f16(cacc[mt][nt], ah, bl[nt]);
                mma_f16(cacc[mt][nt], al, bh[nt]);
                mma_f16(cacc[mt][nt], ah, bh[nt]);
            }
        }
        __syncthreads();
    }

    const int b = m0 >> LOG2L;
    const int tbase = (m0 & (L_ - 1)) + wm0 + g;
#pragma unroll
    for (int nt = 0; nt < 4; nt++) {
        const int d0 = n0 + wn0 + nt * 8 + 2 * c;
        const float bi0 = bias[d0];
        const float bi1 = bias[d0 + 1];
        const size_t row0 = ((size_t)(b * D_ + d0) << LOG2L);
        const size_t row1 = row0 + L_;
#pragma unroll
        for (int mt = 0; mt < 4; mt++) {
            const int t = tbase + mt * 16;
            outT[row0 + t]     = cacc[mt][nt][0] + bi0;
            outT[row1 + t]     = cacc[mt][nt][1] + bi1;
            outT[row0 + t + 8] = cacc[mt][nt][2] + bi0;
            outT[row1 + t + 8] = cacc[mt][nt][3] + bi1;
        }
    }
}

// ---------------- complex helpers ----------------
__device__ __forceinline__ float2 cmul(float2 a, float2 b) {
    return make_float2(a.x * b.x - a.y * b.y, a.x * b.y + a.y * b.x);
}
__device__ __forceinline__ float2 cmulc(float2 a, float2 b) {   // a * conj(b)
    return make_float2(a.x * b.x + a.y * b.y, a.y * b.x - a.x * b.y);
}
__device__ __forceinline__ float2 cadd(float2 a, float2 b) { return make_float2(a.x + b.x, a.y + b.y); }
__device__ __forceinline__ float2 csub(float2 a, float2 b) { return make_float2(a.x - b.x, a.y - b.y); }

#define ZI(i) ((i) + ((i) >> 5))
#define XI(i) ((i) + ((i) >> 5))

// ---------------- fused FFT-correlation + top-k + softmax + gather ----------------
// Forward: 2048-pt complex FFT of q+ik (r11 exact).
// Inverse: conjugate-symmetric spectrum -> 1024-pt complex inverse via the
// irfft packing x[m] = R[2m] + i R[2m+1]. Combine fused with first group.
__global__ __launch_bounds__(256)
void corr_attn_kernel() {
    __shared__ float2 tw[L_ / 2];          // 8 KB
    __shared__ float2 z[L_ + L_ / 32];     // vcol (lower 8KB) + X array (upper)
    __shared__ float2 s[L_ + L_ / 32];     // fwd FFT workspace + spectrum
    __shared__ float  red_v[16];
    __shared__ int    red_i[16];

    const int tid = threadIdx.x;
    const int lane = tid & 31;
    const int warp = tid >> 5;
    const int bd = blockIdx.x;
    const size_t col = (size_t)bd << LOG2L;

    const int l32 = lane;
    const int c32 = l32 + (tid >> 5) * 256;
    const int t1 = tid & 3;
    const int c4 = t1 + (tid >> 2) * 32;
    const int base8 = tid * 8;

    float2* zx = z + 1056;                 // 1024-pt X array (padded XI indexing)

    for (int i = tid; i < L_ / 2; i += 256) tw[i] = g_tw[i];

    float2 zr[8];
#pragma unroll
    for (int q = 0; q < 8; q++)
        zr[q] = make_float2(g_qT[col + tid + 256 * q], g_kT[col + tid + 256 * q]);
    __syncthreads();

    // ======== forward DIF (into s; r11 structure, buffer renamed) ========
#pragma unroll
    for (int q = 0; q < 4; q++) {
        float2 a = zr[q], b = zr[q + 4];
        float2 wv = tw[tid + 256 * q];
        zr[q] = cadd(a, b);
        zr[q + 4] = cmul(csub(a, b), wv);
    }
#pragma unroll
    for (int gg = 0; gg < 8; gg += 4)
#pragma unroll
        for (int q = 0; q < 2; q++) {
            float2 a = zr[gg + q], b = zr[gg + q + 2];
            float2 wv = tw[(tid + 256 * q) << 1];
            zr[gg + q] = cadd(a, b);
            zr[gg + q + 2] = cmul(csub(a, b), wv);
        }
    {
        float2 wv = tw[tid << 2];
#pragma unroll
        for (int p = 0; p < 8; p += 2) {
            float2 a = zr[p], b = zr[p + 1];
            zr[p] = cadd(a, b);
            zr[p + 1] = cmul(csub(a, b), wv);
        }
    }
#pragma unroll
    for (int q = 0; q < 8; q++) s[ZI(tid + 256 * q)] = zr[q];
    __syncthreads();

#pragma unroll
    for (int q = 0; q < 8; q++) zr[q] = s[ZI(c32 + 32 * q)];
#pragma unroll
    for (int q = 0; q < 4; q++) {
        float2 a = zr[q], b = zr[q + 4];
        float2 wv = tw[(l32 + 32 * q) << 3];
        zr[q] = cadd(a, b);
        zr[q + 4] = cmul(csub(a, b), wv);
    }
#pragma unroll
    for (int gg = 0; gg < 8; gg += 4)
#pragma unroll
        for (int q = 0; q < 2; q++) {
            float2 a = zr[gg + q], b = zr[gg + q + 2];
            float2 wv = tw[(l32 + 32 * q) << 4];
            zr[gg + q] = cadd(a, b);
            zr[gg + q + 2] = cmul(csub(a, b), wv);
        }
    {
        float2 wv = tw[l32 << 5];
#pragma unroll
        for (int p = 0; p < 8; p += 2) {
            float2 a = zr[p], b = zr[p + 1];
            zr[p] = cadd(a, b);
            zr[p + 1] = cmul(csub(a, b), wv);
        }
    }
#pragma unroll
    for (int q = 0; q < 8; q++) s[ZI(c32 + 32 * q)] = zr[q];
    __syncthreads();

#pragma unroll
    for (int q = 0; q < 8; q++) zr[q] = s[ZI(c4 + 4 * q)];
#pragma unroll
    for (int q = 0; q < 4; q++) {
        float2 a = zr[q], b = zr[q + 4];
        float2 wv = tw[(t1 + 4 * q) << 6];
        zr[q] = cadd(a, b);
        zr[q + 4] = cmul(csub(a, b), wv);
    }
#pragma unroll
    for (int gg = 0; gg < 8; gg += 4)
#pragma unroll
        for (int q = 0; q < 2; q++) {
            float2 a = zr[gg + q], b = zr[gg + q + 2];
            float2 wv = tw[(t1 + 4 * q) << 7];
            zr[gg + q] = cadd(a, b);
            zr[gg + q + 2] = cmul(csub(a, b), wv);
        }
    {
        float2 wv = tw[t1 << 8];
#pragma unroll
        for (int p = 0; p < 8; p += 2) {
            float2 a = zr[p], b = zr[p + 1];
            zr[p] = cadd(a, b);
            zr[p + 1] = cmul(csub(a, b), wv);
        }
    }
#pragma unroll
    for (int q = 0; q < 8; q++) s[ZI(c4 + 4 * q)] = zr[q];
    __syncthreads();

#pragma unroll
    for (int q = 0; q < 8; q++) zr[q] = s[ZI(base8 + q)];
#pragma unroll
    for (int gg = 0; gg < 8; gg += 4)
#pragma unroll
        for (int q = 0; q < 2; q++) {
            float2 a = zr[gg + q], b = zr[gg + q + 2];
            float2 wv = tw[(q & 1) << 9];
            zr[gg + q] = cadd(a, b);
            zr[gg + q + 2] = cmul(csub(a, b), wv);
        }
#pragma unroll
    for (int p = 0; p < 8; p += 2) {
        float2 a = zr[p], b = zr[p + 1];
        zr[p] = cadd(a, b);
        zr[p + 1] = csub(a, b);
    }
    // zr now = Z at bit-reversed positions base8+q

    // ======== cross-spectrum: S stored IN-REGISTER then to s ========
    // (same math as r11 but computed from the freshly written s after store)
#pragma unroll
    for (int q = 0; q < 8; q++) s[ZI(base8 + q)] = zr[q];
    __syncthreads();

    const float scl = 0.25f / (float)L_;
    for (int p = tid; p < L_; p += 256) {
        int f = __brev((unsigned)p) >> 21;
        int fm = (L_ - f) & (L_ - 1);
        int pm = __brev((unsigned)fm) >> 21;
        float2 Zf = s[ZI(p)];
        float2 Zm = s[ZI(pm)];
        float2 u = make_float2(Zf.x + Zm.x, Zf.y - Zm.y);
        float2 v = make_float2(Zf.x - Zm.x, -Zf.y - Zm.y);
        float2 pr = cmul(u, v);
        z[ZI(p)] = make_float2(-pr.y * scl, pr.x * scl);   // S -> z temporarily
    }
    __syncthreads();
    // copy spectrum back to s (z needed for vcol+X)... avoid copy: swap roles.
    // S now lives in z. vcol/X must NOT clobber z yet -> do combine first, then vload.

    // ======== fused combine + inverse group A (spans 1,2) ========
    // X[j] = (S[k]+S[k+N]) + i*conj(tw[k])*(S[k]-S[k+N]),  j=brev10(k)
    // S[k] at bit-rev-11 pos 2j, S[k+N] at 2j+1 (both in z). Thread owns j=4t..4t+3.
    {
        float2 Sp[8];
#pragma unroll
        for (int e = 0; e < 8; e++) Sp[e] = z[ZI(base8 + e)];
        float2 X[4];
#pragma unroll
        for (int cc = 0; cc < 4; cc++) {
            int j = 4 * tid + cc;
            int k = __brev((unsigned)j) >> 22;   // brev10
            float2 E = cadd(Sp[2 * cc], Sp[2 * cc + 1]);
            float2 Dd = csub(Sp[2 * cc], Sp[2 * cc + 1]);
            float2 O = cmulc(Dd, tw[k]);
            X[cc] = make_float2(E.x - O.y, E.y + O.x);   // E + i*O
        }
        // group A butterflies: span1 (W=1), span2 (pairs (0,2) W=1; (1,3) W=conj tw[512])
        {
            float2 a = X[0], b = X[1];
            X[0] = cadd(a, b); X[1] = csub(a, b);
            a = X[2]; b = X[3];
            X[2] = cadd(a, b); X[3] = csub(a, b);
        }
        {
            float2 bw = X[2];
            float2 a = X[0];
            X[0] = cadd(a, bw); X[2] = csub(a, bw);
            bw = cmulc(X[3], tw[512]);
            a = X[1];
            X[1] = cadd(a, bw); X[3] = csub(a, bw);
        }
        __syncthreads();   // all reads of z(S) complete before X/vcol overwrite z
#pragma unroll
        for (int cc = 0; cc < 4; cc++) zx[XI(4 * tid + cc)] = X[cc];
    }
    // vcol load into lower z (disjoint from zx region)
    float* vcol = (float*)z;
    for (int i = tid; i < L_; i += 256) vcol[i] = g_vT[col + i];
    __syncthreads();

    // ======== inverse groups B..D (4 pts/thread, 2 stages each) ========
    // group B: spans 4,8
    {
        const int j0 = tid & 3;
        const int i0 = j0 + (tid >> 2) * 16;
        float2 a = zx[XI(i0)], b = zx[XI(i0 + 4)], cc = zx[XI(i0 + 8)], d = zx[XI(i0 + 12)];
        float2 W1 = tw[j0 << 8];
        float2 bw = cmulc(b, W1);  b = csub(a, bw);  a = cadd(a, bw);
        float2 dw = cmulc(d, W1);  d = csub(cc, dw); cc = cadd(cc, dw);
        float2 W20 = tw[j0 << 7], W21 = tw[(j0 + 4) << 7];
        float2 cw = cmulc(cc, W20); cc = csub(a, cw); a = cadd(a, cw);
        dw = cmulc(d, W21);         d = csub(b, dw);  b = cadd(b, dw);
        __syncthreads();
        zx[XI(i0)] = a; zx[XI(i0 + 4)] = b; zx[XI(i0 + 8)] = cc; zx[XI(i0 + 12)] = d;
    }
    __syncthreads();
    // group C: spans 16,32
    {
        const int j0 = tid & 15;
        const int i0 = j0 + (tid >> 4) * 64;
        float2 a = zx[XI(i0)], b = zx[XI(i0 + 16)], cc = zx[XI(i0 + 32)], d = zx[XI(i0 + 48)];
        float2 W1 = tw[j0 << 6];
        float2 bw = cmulc(b, W1);  b = csub(a, bw);  a = cadd(a, bw);
        float2 dw = cmulc(d, W1);  d = csub(cc, dw); cc = cadd(cc, dw);
        float2 W20 = tw[j0 << 5], W21 = tw[(j0 + 16) << 5];
        float2 cw = cmulc(cc, W20); cc = csub(a, cw); a = cadd(a, cw);
        dw = cmulc(d, W21);         d = csub(b, dw);  b = cadd(b, dw);
        __syncthreads();
        zx[XI(i0)] = a; zx[XI(i0 + 16)] = b; zx[XI(i0 + 32)] = cc; zx[XI(i0 + 48)] = d;
    }
    __syncthreads();
    // group D: spans 64,128
    {
        const int j0 = tid & 63;
        const int i0 = j0 + (tid >> 6) * 256;
        float2 a = zx[XI(i0)], b = zx[XI(i0 + 64)], cc = zx[XI(i0 + 128)], d = zx[XI(i0 + 192)];
        float2 W1 = tw[j0 << 4];
        float2 bw = cmulc(b, W1);  b = csub(a, bw);  a = cadd(a, bw);
        float2 dw = cmulc(d, W1);  d = csub(cc, dw); cc = cadd(cc, dw);
        float2 W20 = tw[j0 << 3], W21 = tw[(j0 + 64) << 3];
        float2 cw = cmulc(cc, W20); cc = csub(a, cw); a = cadd(a, cw);
        dw = cmulc(d, W21);         d = csub(b, dw);  b = cadd(b, dw);
        __syncthreads();
        zx[XI(i0)] = a; zx[XI(i0 + 64)] = b; zx[XI(i0 + 128)] = cc; zx[XI(i0 + 192)] = d;
    }
    __syncthreads();
    // group E: spans 256,512 (registers; feeds top-k)
    float2 xr[4];
    {
        xr[0] = zx[XI(tid)];
        xr[1] = zx[XI(tid + 256)];
        xr[2] = zx[XI(tid + 512)];
        xr[3] = zx[XI(tid + 768)];
        float2 W1 = tw[tid << 2];
        float2 bw = cmulc(xr[1], W1); xr[1] = csub(xr[0], bw); xr[0] = cadd(xr[0], bw);
        float2 dw = cmulc(xr[3], W1); xr[3] = csub(xr[2], dw); xr[2] = cadd(xr[2], dw);
        float2 W20 = tw[tid << 1], W21 = tw[(tid + 256) << 1];
        float2 cw = cmulc(xr[2], W20); xr[2] = csub(xr[0], cw); xr[0] = cadd(xr[0], cw);
        dw = cmulc(xr[3], W21);        xr[3] = csub(xr[1], dw); xr[1] = cadd(xr[1], dw);
    }
    // xr[h] = x[tid + 256h]; R[2m] = x.x, R[2m+1] = x.y

    // ---- top-15: r5 scheme; idx(q) = 2*tid + 512*(q>>1) + (q&1) ----
    float rv[8];
    rv[0] = xr[0].x; rv[1] = xr[0].y;
    rv[2] = xr[1].x; rv[3] = xr[1].y;
    rv[4] = xr[2].x; rv[5] = xr[2].y;
    rv[6] = xr[3].x; rv[7] = xr[3].y;

    float wsel[KTOP];
    int isel[KTOP];
#pragma unroll 1
    for (int rnd = 0; rnd < KTOP; rnd++) {
        float best = rv[0];
        int bq = 0;
#pragma unroll
        for (int q = 1; q < 8; q++)
            if (rv[q] > best) { best = rv[q]; bq = q; }
        int bi = 2 * tid + 512 * (bq >> 1) + (bq & 1);
#pragma unroll
        for (int off = 16; off > 0; off >>= 1) {
            float ov = __shfl_xor_sync(0xffffffffu, best, off);
            int oi = __shfl_xor_sync(0xffffffffu, bi, off);
            if (ov > best || (ov == best && oi < bi)) { best = ov; bi = oi; }
        }
        const int slot = (rnd & 1) * 8;
        if (lane == 0) { red_v[slot + warp] = best; red_i[slot + warp] = bi; }
        __syncthreads();
        float gb = red_v[slot];
        int gi = red_i[slot];
#pragma unroll
        for (int ww = 1; ww < 8; ww++) {
            float ov = red_v[slot + ww];
            int oi = red_i[slot + ww];
            if (ov > gb || (ov == gb && oi < gi)) { gb = ov; gi = oi; }
        }
        wsel[rnd] = gb;
        isel[rnd] = gi;
        // invalidate winner (constant register indices)
#pragma unroll
        for (int q = 0; q < 8; q++)
            if (gi == 2 * tid + 512 * (q >> 1) + (q & 1)) rv[q] = -FLT_MAX;
    }

    // ---- softmax over the 15 selected (redundant per thread) ----
    float m = wsel[0];
#pragma unroll
    for (int k = 1; k < KTOP; k++) m = fmaxf(m, wsel[k]);
    float sum = 0.0f;
    float wnorm[KTOP];
#pragma unroll
    for (int k = 0; k < KTOP; k++) { float e = __expf(wsel[k] - m); wnorm[k] = e; sum += e; }
    const float inv = 1.0f / sum;
#pragma unroll
    for (int k = 0; k < KTOP; k++) wnorm[k] *= inv;

    // ---- gather: A^T[b,d,l] = sum_k w[k] * v[(l + lag_k) mod L] ----
    for (int l = tid; l < L_; l += 256) {
        float acc = 0.0f;
#pragma unroll
        for (int k = 0; k < KTOP; k++)
            acc = fmaf(wnorm[k], vcol[(l + isel[k]) & (L_ - 1)], acc);
        g_AT[col + l] = acc;
    }
}

// ---------------- transpose (B, D, L) -> (B, L, D) ----------------
__global__ void transpose_kernel(float* __restrict__ A) {
    __shared__ float tile[32][33];
    const int b = blockIdx.z;
    const int l0 = blockIdx.x * 32;
    const int d0 = blockIdx.y * 32;
    const int tx = threadIdx.x, ty = threadIdx.y;
#pragma unroll
    for (int r = 0; r < 32; r += 8)
        tile[ty + r][tx] = g_AT[((size_t)(b * D_ + d0 + ty + r) << LOG2L) + l0 + tx];
    __syncthreads();
#pragma unroll
    for (int r = 0; r < 32; r += 8)
        A[((size_t)(b * L_ + l0 + ty + r)) * D_ + d0 + tx] = tile[tx][ty + r];
}

// ---------------- launch ----------------
extern "C" void kernel_launch(void* const* d_in, const int* in_sizes, int n_in,
                              void* d_out, int out_size) {
    const float* Q   = (const float*)d_in[0];
    const float* K   = (const float*)d_in[1];
    const float* V   = (const float*)d_in[2];
    const float* WQw = (const float*)d_in[3];
    const float* WQb = (const float*)d_in[4];
    const float* WKw = (const float*)d_in[5];
    const float* WKb = (const float*)d_in[6];
    const float* WVw = (const float*)d_in[7];
    const float* WVb = (const float*)d_in[8];
    float* out = (float*)d_out;

    twiddle_init_kernel<<<4, 256>>>();

    dim3 ggrid(B_ * L_ / 128, D_ / 128, 3);   // (128, 4, 3)
    gemm3_fp16_kernel<<<ggrid, 256>>>(Q, K, V, WQw, WKw, WVw, WQb, WKb, WVb);

    corr_attn_kernel<<<B_ * D_, 256>>>();

    dim3 tgrid(L_ / 32, D_ / 32, B_);         // (64, 16, 8)
    transpose_kernel<<<tgrid, dim3(32, 8)>>>(out);
}

// round 14
// speedup vs baseline: 1.1586x; 1.1015x over previous
#include <cuda_runtime.h>
#include <cuda_fp16.h>
#include <math.h>
#include <float.h>

// Problem constants
#define B_   8
#define L_   2048
#define LOG2L 11
#define D_   512
#define DM_  512
#define KTOP 15

// ---------------- device scratch (static allocation only) ----------------
__device__ float g_qT[B_ * D_ * L_];   // (B, D, L)
__device__ float g_kT[B_ * D_ * L_];
__device__ float g_vT[B_ * D_ * L_];
__device__ float g_AT[B_ * D_ * L_];
__device__ float2 g_tw[L_ / 2];        // exp(-2*pi*i*j/L)

// ---------------- twiddle init ----------------
__global__ void twiddle_init_kernel() {
    int j = blockIdx.x * blockDim.x + threadIdx.x;
    if (j < L_ / 2) {
        float sn, cs;
        sincospif((float)j / 1024.0f, &sn, &cs);
        g_tw[j] = make_float2(cs, -sn);
    }
}

// ---------------- FP16 split helpers ----------------
__device__ __forceinline__ unsigned pack_hi(float a, float b) {
    __half2 h = __halves2half2(__float2half_rn(a), __float2half_rn(b));
    return *(unsigned*)&h;
}
__device__ __forceinline__ unsigned pack_lo(float a, float b) {
    float ra = a - __half2float(__float2half_rn(a));
    float rb = b - __half2float(__float2half_rn(b));
    __half2 h = __halves2half2(__float2half_rn(ra), __float2half_rn(rb));
    return *(unsigned*)&h;
}

__device__ __forceinline__ void mma_f16(float c[4], const unsigned a[4], const unsigned b[2]) {
    asm volatile(
        "mma.sync.aligned.m16n8k16.row.col.f32.f16.f16.f32 "
        "{%0,%1,%2,%3}, {%4,%5,%6,%7}, {%8,%9}, {%0,%1,%2,%3};\n"
        : "+f"(c[0]), "+f"(c[1]), "+f"(c[2]), "+f"(c[3])
        : "r"(a[0]), "r"(a[1]), "r"(a[2]), "r"(a[3]), "r"(b[0]), "r"(b[1]));
}

// ---------------- Fused 3-GEMM (fp16 split x3 products, fp32 accum) ----------------
// EXACT r5 champion version.
__global__ __launch_bounds__(256, 2)
void gemm3_fp16_kernel(const float* __restrict__ Qi, const float* __restrict__ Ki,
                       const float* __restrict__ Vi,
                       const float* __restrict__ WQ, const float* __restrict__ WK,
                       const float* __restrict__ WV,
                       const float* __restrict__ bQ, const float* __restrict__ bK,
                       const float* __restrict__ bV) {
    const int z = blockIdx.z;
    const float* X    = (z == 0) ? Qi : ((z == 1) ? Ki : Vi);
    const float* W    = (z == 0) ? WQ : ((z == 1) ? WK : WV);
    const float* bias = (z == 0) ? bQ : ((z == 1) ? bK : bV);
    float* outT       = (z == 0) ? g_qT : ((z == 1) ? g_kT : g_vT);

    __shared__ unsigned As2h[128][9], As2l[128][9];
    __shared__ unsigned Bs2h[8][132], Bs2l[8][132];

    const int tid = threadIdx.x;
    const int lane = tid & 31;
    const int w = tid >> 5;
    const int wm0 = (w & 1) * 64;
    const int wn0 = (w >> 1) * 32;
    const int g = lane >> 2;
    const int c = lane & 3;
    const int m0 = blockIdx.x * 128;
    const int n0 = blockIdx.y * 128;

    const int rowA = tid >> 2;
    const int kqA  = (tid & 3) << 2;
    const int pB   = tid >> 5;
    const int nqB  = (lane) << 2;
    const float* pA0 = &X[(size_t)(m0 + rowA) * DM_ + kqA];
    const float* pA1 = pA0 + (size_t)64 * DM_;
    const float* pB0 = &W[(size_t)(2 * pB) * D_ + n0 + nqB];
    const float* pB1 = pB0 + D_;

    float cacc[4][4][4];
#pragma unroll
    for (int mt = 0; mt < 4; mt++)
#pragma unroll
        for (int nt = 0; nt < 4; nt++)
#pragma unroll
            for (int i = 0; i < 4; i++) cacc[mt][nt][i] = 0.0f;

    float4 av0 = *(const float4*)pA0;
    float4 av1 = *(const float4*)pA1;
    float4 bv0 = *(const float4*)pB0;
    float4 bv1 = *(const float4*)pB1;

#pragma unroll 1
    for (int k0 = 0; k0 < DM_; k0 += 16) {
        const int kp = kqA >> 1;
        As2h[rowA][kp]          = pack_hi(av0.x, av0.y);
        As2h[rowA][kp + 1]      = pack_hi(av0.z, av0.w);
        As2l[rowA][kp]          = pack_lo(av0.x, av0.y);
        As2l[rowA][kp + 1]      = pack_lo(av0.z, av0.w);
        As2h[rowA + 64][kp]     = pack_hi(av1.x, av1.y);
        As2h[rowA + 64][kp + 1] = pack_hi(av1.z, av1.w);
        As2l[rowA + 64][kp]     = pack_lo(av1.x, av1.y);
        As2l[rowA + 64][kp + 1] = pack_lo(av1.z, av1.w);
        {
            uint4 uh = make_uint4(pack_hi(bv0.x, bv1.x), pack_hi(bv0.y, bv1.y),
                                  pack_hi(bv0.z, bv1.z), pack_hi(bv0.w, bv1.w));
            uint4 ul = make_uint4(pack_lo(bv0.x, bv1.x), pack_lo(bv0.y, bv1.y),
                                  pack_lo(bv0.z, bv1.z), pack_lo(bv0.w, bv1.w));
            *(uint4*)&Bs2h[pB][nqB] = uh;
            *(uint4*)&Bs2l[pB][nqB] = ul;
        }
        __syncthreads();

        if (k0 + 16 < DM_) {
            av0 = *(const float4*)(pA0 + k0 + 16);
            av1 = *(const float4*)(pA1 + k0 + 16);
            bv0 = *(const float4*)(pB0 + (size_t)(k0 + 16) * D_);
            bv1 = *(const float4*)(pB1 + (size_t)(k0 + 16) * D_);
        }

        unsigned bh[4][2], bl[4][2];
#pragma unroll
        for (int nt = 0; nt < 4; nt++) {
            int cn = wn0 + nt * 8 + g;
            bh[nt][0] = Bs2h[c][cn];
            bh[nt][1] = Bs2h[c + 4][cn];
            bl[nt][0] = Bs2l[c][cn];
            bl[nt][1] = Bs2l[c + 4][cn];
        }
#pragma unroll
        for (int mt = 0; mt < 4; mt++) {
            int row = wm0 + mt * 16 + g;
            unsigned ah[4], al[4];
            ah[0] = As2h[row][c];
            ah[1] = As2h[row + 8][c];
            ah[2] = As2h[row][c + 4];
            ah[3] = As2h[row + 8][c + 4];
            al[0] = As2l[row][c];
            al[1] = As2l[row + 8][c];
            al[2] = As2l[row][c + 4];
            al[3] = As2l[row + 8][c + 4];
#pragma unroll
            for (int nt = 0; nt < 4; nt++) {
                mma_f16(cacc[mt][nt], ah, bl[nt]);
                mma_f16(cacc[mt][nt], al, bh[nt]);
                mma_f16(cacc[mt][nt], ah, bh[nt]);
            }
        }
        __syncthreads();
    }

    const int b = m0 >> LOG2L;
    const int tbase = (m0 & (L_ - 1)) + wm0 + g;
#pragma unroll
    for (int nt = 0; nt < 4; nt++) {
        const int d0 = n0 + wn0 + nt * 8 + 2 * c;
        const float bi0 = bias[d0];
        const float bi1 = bias[d0 + 1];
        const size_t row0 = ((size_t)(b * D_ + d0) << LOG2L);
        const size_t row1 = row0 + L_;
#pragma unroll
        for (int mt = 0; mt < 4; mt++) {
            const int t = tbase + mt * 16;
            outT[row0 + t]     = cacc[mt][nt][0] + bi0;
            outT[row1 + t]     = cacc[mt][nt][1] + bi1;
            outT[row0 + t + 8] = cacc[mt][nt][2] + bi0;
            outT[row1 + t + 8] = cacc[mt][nt][3] + bi1;
        }
    }
}

// ---------------- complex helpers ----------------
__device__ __forceinline__ float2 cmul(float2 a, float2 b) {
    return make_float2(a.x * b.x - a.y * b.y, a.x * b.y + a.y * b.x);
}
__device__ __forceinline__ float2 cmulc(float2 a, float2 b) {   // a * conj(b)
    return make_float2(a.x * b.x + a.y * b.y, a.y * b.x - a.x * b.y);
}
__device__ __forceinline__ float2 cadd(float2 a, float2 b) { return make_float2(a.x + b.x, a.y + b.y); }
__device__ __forceinline__ float2 csub(float2 a, float2 b) { return make_float2(a.x - b.x, a.y - b.y); }

#define ZI(i) ((i) + ((i) >> 5))
#define XI(i) ((i) + ((i) >> 5))

// forward DIF butterfly: (a,b) -> (a+b, (a-b)*w)
#define BF_F(A, B, W) do { float2 _t = csub(A, B); A = cadd(A, B); B = cmul(_t, W); } while (0)
// inverse DIT butterfly: (a,b) -> (a + b*conj(w), a - b*conj(w))
#define BF_I(A, B, W) do { float2 _bw = cmulc(B, W); B = csub(A, _bw); A = cadd(A, _bw); } while (0)

// ---------------- fused FFT-correlation + top-k + softmax + gather ----------------
// 128 threads, 16 points/thread. Forward 2048-pt FFT: 3 register groups (4/4/3
// stages), 2 smem exchanges. Inverse: conj-symmetric spectrum -> 1024-pt complex
// inverse (irfft packing), 8 pts/thread, combine fused with first group.
__global__ __launch_bounds__(128)
void corr_attn_kernel() {
    __shared__ float2 tw[L_ / 2];          // 8 KB
    __shared__ float2 z[L_ + L_ / 32];     // S / vcol (lower) + X (upper)
    __shared__ float2 s[L_ + L_ / 32];     // forward FFT workspace
    __shared__ float  red_v[8];
    __shared__ int    red_i[8];

    const int tid = threadIdx.x;           // 0..127
    const int lane = tid & 31;
    const int warp = tid >> 5;              // 0..3
    const int bd = blockIdx.x;
    const size_t col = (size_t)bd << LOG2L;

    float2* zx = z + 1056;                 // 1024-pt X array (XI-padded)

    for (int i = tid; i < L_ / 2; i += 128) tw[i] = g_tw[i];

    float2 zr[16];
#pragma unroll
    for (int q = 0; q < 16; q++)
        zr[q] = make_float2(g_qT[col + tid + 128 * q], g_kT[col + tid + 128 * q]);
    __syncthreads();   // twiddles ready

    // ======== forward DIF, group 1: spans 1024/512/256/128 (registers) ========
#pragma unroll
    for (int q = 0; q < 8; q++) {
        float2 wv = tw[tid + 128 * q];
        BF_F(zr[q], zr[q + 8], wv);
    }
#pragma unroll
    for (int h = 0; h < 16; h += 8)
#pragma unroll
        for (int q = 0; q < 4; q++) {
            float2 wv = tw[(tid + 128 * q) << 1];
            BF_F(zr[h + q], zr[h + q + 4], wv);
        }
#pragma unroll
    for (int h = 0; h < 16; h += 4)
#pragma unroll
        for (int q = 0; q < 2; q++) {
            float2 wv = tw[(tid + 128 * q) << 2];
            BF_F(zr[h + q], zr[h + q + 2], wv);
        }
    {
        float2 wv = tw[tid << 3];
#pragma unroll
        for (int p = 0; p < 16; p += 2) BF_F(zr[p], zr[p + 1], wv);
    }
#pragma unroll
    for (int q = 0; q < 16; q++) s[ZI(tid + 128 * q)] = zr[q];
    __syncthreads();

    // ======== group 2: spans 64/32/16/8 (stride-8 ownership) ========
    const int c8 = (tid & 7) + (tid >> 3) * 128;
#pragma unroll
    for (int q = 0; q < 16; q++) zr[q] = s[ZI(c8 + 8 * q)];
#pragma unroll
    for (int q = 0; q < 8; q++) {
        float2 wv = tw[((tid & 7) + 8 * q) << 4];
        BF_F(zr[q], zr[q + 8], wv);
    }
#pragma unroll
    for (int h = 0; h < 16; h += 8)
#pragma unroll
        for (int q = 0; q < 4; q++) {
            float2 wv = tw[((tid & 7) + 8 * q) << 5];
            BF_F(zr[h + q], zr[h + q + 4], wv);
        }
#pragma unroll
    for (int h = 0; h < 16; h += 4)
#pragma unroll
        for (int q = 0; q < 2; q++) {
            float2 wv = tw[((tid & 7) + 8 * q) << 6];
            BF_F(zr[h + q], zr[h + q + 2], wv);
        }
    {
        float2 wv = tw[(tid & 7) << 7];
#pragma unroll
        for (int p = 0; p < 16; p += 2) BF_F(zr[p], zr[p + 1], wv);
    }
#pragma unroll
    for (int q = 0; q < 16; q++) s[ZI(c8 + 8 * q)] = zr[q];
    __syncthreads();

    // ======== group 3: spans 4/2/1 (contiguous ownership) ========
    const int base16 = tid * 16;
#pragma unroll
    for (int q = 0; q < 16; q++) zr[q] = s[ZI(base16 + q)];
#pragma unroll
    for (int h = 0; h < 16; h += 8)
#pragma unroll
        for (int q = 0; q < 4; q++) {
            float2 wv = tw[q << 8];
            BF_F(zr[h + q], zr[h + q + 4], wv);
        }
#pragma unroll
    for (int h = 0; h < 16; h += 4)
#pragma unroll
        for (int q = 0; q < 2; q++) {
            float2 wv = tw[q << 9];
            BF_F(zr[h + q], zr[h + q + 2], wv);
        }
#pragma unroll
    for (int p = 0; p < 16; p += 2) {
        float2 a = zr[p], b = zr[p + 1];
        zr[p] = cadd(a, b);
        zr[p + 1] = csub(a, b);
    }
#pragma unroll
    for (int q = 0; q < 16; q++) s[ZI(base16 + q)] = zr[q];
    __syncthreads();
    // s = Z in bit-reversed-11 order

    // ======== cross-spectrum: S[p] from Z[p], Z[pm]; s -> z ========
    const float scl = 0.25f / (float)L_;
#pragma unroll
    for (int it = 0; it < 16; it++) {
        int p = tid + 128 * it;
        int f = __brev((unsigned)p) >> 21;
        int fm = (L_ - f) & (L_ - 1);
        int pm = __brev((unsigned)fm) >> 21;
        float2 Zf = s[ZI(p)], Zm = s[ZI(pm)];
        float2 u = make_float2(Zf.x + Zm.x, Zf.y - Zm.y);
        float2 v = make_float2(Zf.x - Zm.x, -Zf.y - Zm.y);
        float2 pr = cmul(u, v);
        z[ZI(p)] = make_float2(-pr.y * scl, pr.x * scl);
    }
    __syncthreads();

    // ======== fused combine + inverse group A (spans 1,2) ========
    // X[j] = (S[k]+S[k+N]) + i*conj(tw[k])*(S[k]-S[k+N]), j=brev10(k);
    // S[k] at bit-rev-11 pos 2j, S[k+N] at 2j+1. Thread owns j = 8t..8t+7.
    float2 X[8];
    {
        float2 Sp[16];
#pragma unroll
        for (int e = 0; e < 16; e++) Sp[e] = z[ZI(base16 + e)];
#pragma unroll
        for (int cc = 0; cc < 8; cc++) {
            int j = 8 * tid + cc;
            int k = __brev((unsigned)j) >> 22;   // brev10
            float2 E = cadd(Sp[2 * cc], Sp[2 * cc + 1]);
            float2 Dd = csub(Sp[2 * cc], Sp[2 * cc + 1]);
            float2 O = cmulc(Dd, tw[k]);
            X[cc] = make_float2(E.x - O.y, E.y + O.x);   // E + i*O
        }
        // span 1 (W=1)
#pragma unroll
        for (int p = 0; p < 8; p += 2) {
            float2 a = X[p], b = X[p + 1];
            X[p] = cadd(a, b);
            X[p + 1] = csub(a, b);
        }
        // span 2: pairs (cc, cc+2), W = conj tw[(cc&1)<<9]
#pragma unroll
        for (int h = 0; h < 8; h += 4)
#pragma unroll
            for (int q = 0; q < 2; q++) {
                float2 wv = tw[q << 9];
                BF_I(X[h + q], X[h + q + 2], wv);
            }
    }
    __syncthreads();   // all S reads done -> z reusable for vcol + zx
#pragma unroll
    for (int cc = 0; cc < 8; cc++) zx[XI(8 * tid + cc)] = X[cc];

    float* vcol = (float*)z;
    for (int i = tid; i < L_; i += 128) vcol[i] = g_vT[col + i];
    __syncthreads();

    // ======== inverse group B: spans 4/8/16 (stride-4 ownership) ========
    {
        const int c4b = (tid & 3) + (tid >> 2) * 32;
        float2 xr[8];
#pragma unroll
        for (int q = 0; q < 8; q++) xr[q] = zx[XI(c4b + 4 * q)];
        {
            float2 wv = tw[(tid & 3) << 8];
#pragma unroll
            for (int p = 0; p < 8; p += 2) BF_I(xr[p], xr[p + 1], wv);
        }
#pragma unroll
        for (int h = 0; h < 8; h += 4)
#pragma unroll
            for (int q = 0; q < 2; q++) {
                float2 wv = tw[((tid & 3) + 4 * q) << 7];
                BF_I(xr[h + q], xr[h + q + 2], wv);
            }
#pragma unroll
        for (int q = 0; q < 4; q++) {
            float2 wv = tw[((tid & 3) + 4 * q) << 6];
            BF_I(xr[q], xr[q + 4], wv);
        }
#pragma unroll
        for (int q = 0; q < 8; q++) zx[XI(c4b + 4 * q)] = xr[q];
    }
    __syncthreads();

    // ======== inverse group C: spans 32/64/128 (stride-32 ownership) ========
    {
        const int c32b = (tid & 31) + (tid >> 5) * 256;
        float2 xr[8];
#pragma unroll
        for (int q = 0; q < 8; q++) xr[q] = zx[XI(c32b + 32 * q)];
        {
            float2 wv = tw[(tid & 31) << 5];
#pragma unroll
            for (int p = 0; p < 8; p += 2) BF_I(xr[p], xr[p + 1], wv);
        }
#pragma unroll
        for (int h = 0; h < 8; h += 4)
#pragma unroll
            for (int q = 0; q < 2; q++) {
                float2 wv = tw[((tid & 31) + 32 * q) << 4];
                BF_I(xr[h + q], xr[h + q + 2], wv);
            }
#pragma unroll
        for (int q = 0; q < 4; q++) {
            float2 wv = tw[((tid & 31) + 32 * q) << 3];
            BF_I(xr[q], xr[q + 4], wv);
        }
#pragma unroll
        for (int q = 0; q < 8; q++) zx[XI(c32b + 32 * q)] = xr[q];
    }
    __syncthreads();

    // ======== inverse group D: spans 256/512 (stride-128, registers) ========
    float2 xr[8];
#pragma unroll
    for (int q = 0; q < 8; q++) xr[q] = zx[XI(tid + 128 * q)];
#pragma unroll
    for (int h = 0; h < 8; h += 4)
#pragma unroll
        for (int q = 0; q < 2; q++) {
            float2 wv = tw[(tid + 128 * q) << 2];
            BF_I(xr[h + q], xr[h + q + 2], wv);
        }
#pragma unroll
    for (int q = 0; q < 4; q++) {
        float2 wv = tw[(tid + 128 * q) << 1];
        BF_I(xr[q], xr[q + 4], wv);
    }
    // xr[q] = x[tid + 128q]; R[2m] = x.x, R[2m+1] = x.y

    // ---- top-15 (r5 scheme, 4 warps); idx = 2*tid + 256*q + comp ----
    float rv[16];
#pragma unroll
    for (int q = 0; q < 8; q++) { rv[2 * q] = xr[q].x; rv[2 * q + 1] = xr[q].y; }

    float wsel[KTOP];
    int isel[KTOP];
#pragma unroll 1
    for (int rnd = 0; rnd < KTOP; rnd++) {
        float best = rv[0];
        int bq = 0;
#pragma unroll
        for (int q = 1; q < 16; q++)
            if (rv[q] > best) { best = rv[q]; bq = q; }
        int bi = 2 * tid + 256 * (bq >> 1) + (bq & 1);
#pragma unroll
        for (int off = 16; off > 0; off >>= 1) {
            float ov = __shfl_xor_sync(0xffffffffu, best, off);
            int oi = __shfl_xor_sync(0xffffffffu, bi, off);
            if (ov > best || (ov == best && oi < bi)) { best = ov; bi = oi; }
        }
        const int slot = (rnd & 1) * 4;
        if (lane == 0) { red_v[slot + warp] = best; red_i[slot + warp] = bi; }
        __syncthreads();
        float gb = red_v[slot];
        int gi = red_i[slot];
#pragma unroll
        for (int ww = 1; ww < 4; ww++) {
            float ov = red_v[slot + ww];
            int oi = red_i[slot + ww];
            if (ov > gb || (ov == gb && oi < gi)) { gb = ov; gi = oi; }
        }
        wsel[rnd] = gb;
        isel[rnd] = gi;
        // invalidate winner (constant register indices)
#pragma unroll
        for (int q = 0; q < 8; q++) {
            if (gi == 2 * tid + 256 * q)     rv[2 * q]     = -FLT_MAX;
            if (gi == 2 * tid + 256 * q + 1) rv[2 * q + 1] = -FLT_MAX;
        }
    }

    // ---- softmax over the 15 selected (redundant per thread) ----
    float m = wsel[0];
#pragma unroll
    for (int k = 1; k < KTOP; k++) m = fmaxf(m, wsel[k]);
    float sum = 0.0f;
    float wnorm[KTOP];
#pragma unroll
    for (int k = 0; k < KTOP; k++) { float e = __expf(wsel[k] - m); wnorm[k] = e; sum += e; }
    const float inv = 1.0f / sum;
#pragma unroll
    for (int k = 0; k < KTOP; k++) wnorm[k] *= inv;

    // ---- gather: A^T[b,d,l] = sum_k w[k] * v[(l + lag_k) mod L] ----
    for (int l = tid; l < L_; l += 128) {
        float acc = 0.0f;
#pragma unroll
        for (int k = 0; k < KTOP; k++)
            acc = fmaf(wnorm[k], vcol[(l + isel[k]) & (L_ - 1)], acc);
        g_AT[col + l] = acc;
    }
}

// ---------------- transpose (B, D, L) -> (B, L, D) ----------------
__global__ void transpose_kernel(float* __restrict__ A) {
    __shared__ float tile[32][33];
    const int b = blockIdx.z;
    const int l0 = blockIdx.x * 32;
    const int d0 = blockIdx.y * 32;
    const int tx = threadIdx.x, ty = threadIdx.y;
#pragma unroll
    for (int r = 0; r < 32; r += 8)
        tile[ty + r][tx] = g_AT[((size_t)(b * D_ + d0 + ty + r) << LOG2L) + l0 + tx];
    __syncthreads();
#pragma unroll
    for (int r = 0; r < 32; r += 8)
        A[((size_t)(b * L_ + l0 + ty + r)) * D_ + d0 + tx] = tile[tx][ty + r];
}

// ---------------- launch ----------------
extern "C" void kernel_launch(void* const* d_in, const int* in_sizes, int n_in,
                              void* d_out, int out_size) {
    const float* Q   = (const float*)d_in[0];
    const float* K   = (const float*)d_in[1];
    const float* V   = (const float*)d_in[2];
    const float* WQw = (const float*)d_in[3];
    const float* WQb = (const float*)d_in[4];
    const float* WKw = (const float*)d_in[5];
    const float* WKb = (const float*)d_in[6];
    const float* WVw = (const float*)d_in[7];
    const float* WVb = (const float*)d_in[8];
    float* out = (float*)d_out;

    twiddle_init_kernel<<<4, 256>>>();

    dim3 ggrid(B_ * L_ / 128, D_ / 128, 3);   // (128, 4, 3)
    gemm3_fp16_kernel<<<ggrid, 256>>>(Q, K, V, WQw, WKw, WVw, WQb, WKb, WVb);

    corr_attn_kernel<<<B_ * D_, 128>>>();

    dim3 tgrid(L_ / 32, D_ / 32, B_);         // (64, 16, 8)
    transpose_kernel<<<tgrid, dim3(32, 8)>>>(out);
}